// round 12
// baseline (speedup 1.0000x reference)
#include <cuda_runtime.h>
#include <math.h>

#define BB 4
#define NN 8192
#define MM 8192
#define FEAT 64
#define KNN 16
#define K4 4
#define EPS 1e-5f
#define QPB 16     // queries per mlp block
#define BINS 4096  // 12-bit morton (4 bits/dim)
#define SUPER 2048 // points per slice (one super per slice-thread)
#define SUBS 32    // 64-point subtiles per super
#define NSUB 128   // subtiles total

typedef unsigned long long u64;
typedef unsigned int u32;

// ---------------- order-preserving float<->uint ----------------
__device__ __forceinline__ u32 f2ord(float f) {
    u32 u = __float_as_uint(f);
    return u ^ (u32)(((int)u >> 31) | 0x80000000);
}
__device__ __forceinline__ float ord2f(u32 o) {
    return __uint_as_float(o ^ (u32)(((int)(~o) >> 31) | 0x80000000));
}

// ---------------- scratch (static device globals; zero-initialized at load) ----------------
__device__ float g_w0f[FEAT * 3];
__device__ float g_b0f[FEAT];
__device__ float g_w1t[FEAT * FEAT];
__device__ float g_b1f[FEAT];
__device__ int   g_knn[BB * NN * KNN];
__device__ float g_lft[BB * MM * FEAT];   // local_feat transposed to (B, M, FEAT)
// sorts (hist zeroed + bbo re-inited by scan_kernel -> graph-replay invariant)
__device__ int   g_hist[BB][BINS];
__device__ int   g_base[BB][BINS];
__device__ unsigned short g_key[BB][NN];
__device__ int   g_perm[BB][NN];          // sorted pos -> original n
__device__ float g_qs[BB][3][NN];
__device__ int   g_ohist[BB][BINS];
__device__ int   g_obase[BB][BINS];
__device__ unsigned short g_okey[BB][MM];
__device__ int   g_operm[BB][MM];         // sorted pos -> original m
__device__ float4 g_opts[BB][MM];         // sorted (x,y,z,o2)
__device__ u32   g_bbo[BB][NSUB][8];      // per-subtile AABB, ord-encoded [mnx,mny,mnz,mxx,mxy,mxz,pad,pad]

// ---------------- morton helpers (4 bits/dim) ----------------
__device__ __forceinline__ int spread4(int v) {
    return (v & 1) | ((v & 2) << 2) | ((v & 4) << 4) | ((v & 8) << 6);
}
__device__ __forceinline__ int morton_key(float x, float y, float z) {
    int ux = min(15, max(0, (int)((x + 4.0f) * 2.0f)));
    int uy = min(15, max(0, (int)((y + 4.0f) * 2.0f)));
    int uz = min(15, max(0, (int)((z + 4.0f) * 2.0f)));
    return spread4(ux) | (spread4(uy) << 1) | (spread4(uz) << 2);
}

// ---------------- launch 0: keys for queries AND points ----------------
__global__ void __launch_bounds__(256) keys_kernel(const float* __restrict__ q,
                                                   const float* __restrict__ o) {
    int b = blockIdx.y;
    int n = blockIdx.x * 256 + threadIdx.x;
    float qx = q[((size_t)(b * 3 + 0)) * NN + n];
    float qy = q[((size_t)(b * 3 + 1)) * NN + n];
    float qz = q[((size_t)(b * 3 + 2)) * NN + n];
    int kq = morton_key(qx, qy, qz);
    g_key[b][n] = (unsigned short)kq;
    atomicAdd(&g_hist[b][kq], 1);

    float ox = o[((size_t)(b * 3 + 0)) * MM + n];
    float oy = o[((size_t)(b * 3 + 1)) * MM + n];
    float oz = o[((size_t)(b * 3 + 2)) * MM + n];
    int ko = morton_key(ox, oy, oz);
    g_okey[b][n] = (unsigned short)ko;
    atomicAdd(&g_ohist[b][ko], 1);
}

// ---------------- launch 1: scan both hists, re-zero them, init bbox accumulators ----------------
__global__ void __launch_bounds__(1024) scan_kernel() {
    __shared__ int wsum[32];
    int b = blockIdx.x;
    int which = blockIdx.y;
    int (*hist)[BINS] = which ? g_ohist : g_hist;
    int (*base)[BINS] = which ? g_obase : g_base;
    int t = threadIdx.x;
    int lane = t & 31;
    int wid = t >> 5;
    int local[BINS / 1024];
    int s = 0;
#pragma unroll
    for (int i = 0; i < BINS / 1024; i++) {
        local[i] = hist[b][t * (BINS / 1024) + i];
        s += local[i];
    }
    int incl = s;
#pragma unroll
    for (int off = 1; off < 32; off <<= 1) {
        int v = __shfl_up_sync(0xffffffffu, incl, off);
        if (lane >= off) incl += v;
    }
    if (lane == 31) wsum[wid] = incl;
    __syncthreads();
    if (t < 32) {
        int v = wsum[t];
        int iw = v;
#pragma unroll
        for (int off = 1; off < 32; off <<= 1) {
            int u = __shfl_up_sync(0xffffffffu, iw, off);
            if (t >= off) iw += u;
        }
        wsum[t] = iw - v;  // exclusive warp offset
    }
    __syncthreads();
    int run = wsum[wid] + (incl - s);
#pragma unroll
    for (int i = 0; i < BINS / 1024; i++) {
        base[b][t * (BINS / 1024) + i] = run;
        run += local[i];
        hist[b][t * (BINS / 1024) + i] = 0;   // ready for next graph replay
    }
    // init bbox accumulators (NSUB*8 = 1024 entries; one per thread; which==1 side)
    if (which) {
        int sub = t >> 3, f = t & 7;
        g_bbo[b][sub][f] = (f < 3) ? 0xFFFFFFFFu : 0u;   // mins -> +inf-ord, maxes -> 0
    }
}

// ---------------- launch 2: scatter queries AND points (+ bbox atomics) ----------------
__global__ void __launch_bounds__(256) scatters_kernel(const float* __restrict__ q,
                                                       const float* __restrict__ o) {
    int b = blockIdx.y;
    int n = blockIdx.x * 256 + threadIdx.x;

    int kq = g_key[b][n];
    int pq = atomicAdd(&g_base[b][kq], 1);
    g_perm[b][pq] = n;
    g_qs[b][0][pq] = q[((size_t)(b * 3 + 0)) * NN + n];
    g_qs[b][1][pq] = q[((size_t)(b * 3 + 1)) * NN + n];
    g_qs[b][2][pq] = q[((size_t)(b * 3 + 2)) * NN + n];

    int ko = g_okey[b][n];
    int po = atomicAdd(&g_obase[b][ko], 1);
    g_operm[b][po] = n;
    float x = o[((size_t)(b * 3 + 0)) * MM + n];
    float y = o[((size_t)(b * 3 + 1)) * MM + n];
    float z = o[((size_t)(b * 3 + 2)) * MM + n];
    // reference rounding: o2 = (x*x + y*y) + z*z
    float o2 = __fadd_rn(__fadd_rn(__fmul_rn(x, x), __fmul_rn(y, y)), __fmul_rn(z, z));
    g_opts[b][po] = make_float4(x, y, z, o2);

    int sub = po >> 6;
    atomicMin(&g_bbo[b][sub][0], f2ord(x));
    atomicMin(&g_bbo[b][sub][1], f2ord(y));
    atomicMin(&g_bbo[b][sub][2], f2ord(z));
    atomicMax(&g_bbo[b][sub][3], f2ord(x));
    atomicMax(&g_bbo[b][sub][4], f2ord(y));
    atomicMax(&g_bbo[b][sub][5], f2ord(z));
}

// ---------------- launch 3: fused KNN, 4 slices/query (PROFILED SLOT) ----------------
__device__ __forceinline__ float dist_key(float qx, float qy, float qz, float q2,
                                          const float4& o) {
    float cross = __fmaf_rn(o.z, qz, __fmaf_rn(o.y, qy, __fmul_rn(o.x, qx)));
    return __fsub_rn(__fadd_rn(q2, o.w), __fmul_rn(2.0f, cross));
}

// Composed (value,index) u64 key: branch-free select chain; ordering ==
// jax.lax.top_k stable semantics -> scan-order invariant (validated R7/R10/R11).
__device__ __forceinline__ void topk_insert(u64 (&k)[KNN], float& d15f, float sv, int om) {
    if (sv <= d15f) {
        u64 kv = ((u64)f2ord(sv) << 32) | (u32)om;
        if (kv < k[KNN - 1]) {
#pragma unroll
            for (int jj = KNN - 1; jj > 0; --jj) {
                bool sh = kv < k[jj - 1];
                bool he = (kv < k[jj]) && !sh;
                k[jj] = sh ? k[jj - 1] : (he ? kv : k[jj]);
            }
            if (kv < k[0]) k[0] = kv;
            d15f = ord2f((u32)(k[KNN - 1] >> 32));
        }
    }
}

__device__ __forceinline__ u64 u64mn(u64 a, u64 b) { return a < b ? a : b; }
__device__ __forceinline__ u64 u64mx(u64 a, u64 b) { return a > b ? a : b; }

// Merge own ascending 16-list with partner lane's (lane^dist): bitonic
// half-cleaner (c[i] = min(A[i], B[15-i]) = the 16 smallest of the union,
// bitonic) + 4 cleanup stages -> ascending. Both lanes get the same result.
__device__ __forceinline__ void merge_across(u64 (&k)[KNN], int dist) {
    u64 c[KNN];
#pragma unroll
    for (int i = 0; i < KNN; i++) {
        u64 p = __shfl_xor_sync(0xffffffffu, k[KNN - 1 - i], dist);
        c[i] = u64mn(k[i], p);
    }
#pragma unroll
    for (int d = 8; d >= 1; d >>= 1) {
#pragma unroll
        for (int i = 0; i < KNN; i++) {
            if (!(i & d)) {
                u64 lo = u64mn(c[i], c[i + d]);
                u64 hi = u64mx(c[i], c[i + d]);
                c[i] = lo;
                c[i + d] = hi;
            }
        }
    }
#pragma unroll
    for (int i = 0; i < KNN; i++) k[i] = c[i];
}

__global__ void __launch_bounds__(128) knn_kernel() {
    int b = blockIdx.y;
    int tid = threadIdx.x;
    int lane = tid & 31;
    int q = lane & 7;       // query within 8-lane group
    int sl = lane >> 3;     // slice 0..3
    int wrp = tid >> 5;

    int n = blockIdx.x * 32 + wrp * 8 + q;   // sorted query position
    float qx = g_qs[b][0][n];
    float qy = g_qs[b][1][n];
    float qz = g_qs[b][2][n];
    float q2 = __fadd_rn(__fadd_rn(__fmul_rn(qx, qx), __fmul_rn(qy, qy)), __fmul_rn(qz, qz));

    u64 k[KNN];
    u64 sent = ((u64)f2ord(3.0e38f) << 32) | 0xFFFFFFFFu;  // finite value field
#pragma unroll
    for (int j = 0; j < KNN; j++) k[j] = sent;
    float d15f = 3.0e38f;

    int homesuper = n >> 11;                 // uniform within warp
    int sp = (homesuper + sl) & (MM / SUPER - 1);
    int base = sp * SUPER;
    int homesub = (n >> 6) & (SUBS - 1);     // uniform within warp

    for (int ss = 0; ss < SUBS; ss++) {
        int sub = (homesub + ss) & (SUBS - 1);
        // shared prune bound T = min over the 4 slices of this query's local d15
        // (valid upper bound on the global 16th; skipping key > T never drops
        //  a final top-16 member)
        float T = d15f;
        T = fminf(T, __shfl_xor_sync(0xffffffffu, T, 8));
        T = fminf(T, __shfl_xor_sync(0xffffffffu, T, 16));

        int gt = sp * SUBS + sub;
        uint4 bba = *(const uint4*)&g_bbo[b][gt][0];
        uint2 bbb = *(const uint2*)&g_bbo[b][gt][4];
        float gx = fmaxf(0.f, fmaxf(ord2f(bba.x) - qx, qx - ord2f(bba.w)));
        float gy = fmaxf(0.f, fmaxf(ord2f(bba.y) - qy, qy - ord2f(bbb.x)));
        float gz = fmaxf(0.f, fmaxf(ord2f(bba.z) - qz, qz - ord2f(bbb.y)));
        float mind2 = fmaf(gx, gx, fmaf(gy, gy, gz * gz));
        if (!__any_sync(0xffffffffu, mind2 <= T + 1e-3f)) continue;  // margin >> rounding slack

        int pb = base + (sub << 6);
        for (int j = 0; j < 64; j += 4) {
            float4 o0 = __ldg(&g_opts[b][pb + j + 0]);
            float4 o1 = __ldg(&g_opts[b][pb + j + 1]);
            float4 o2 = __ldg(&g_opts[b][pb + j + 2]);
            float4 o3 = __ldg(&g_opts[b][pb + j + 3]);
            float s0 = dist_key(qx, qy, qz, q2, o0);
            float s1 = dist_key(qx, qy, qz, q2, o1);
            float s2 = dist_key(qx, qy, qz, q2, o2);
            float s3 = dist_key(qx, qy, qz, q2, o3);
            float mn = fminf(fminf(s0, s1), fminf(s2, s3));
            if (__any_sync(0xffffffffu, mn <= T)) {
                if (s0 <= T) topk_insert(k, d15f, s0, __ldg(&g_operm[b][pb + j + 0]));
                if (s1 <= T) topk_insert(k, d15f, s1, __ldg(&g_operm[b][pb + j + 1]));
                if (s2 <= T) topk_insert(k, d15f, s2, __ldg(&g_operm[b][pb + j + 2]));
                if (s3 <= T) topk_insert(k, d15f, s3, __ldg(&g_operm[b][pb + j + 3]));
            }
        }
    }

    // merge the 4 slices' lists -> global top-16 (same in all 4 lanes)
    merge_across(k, 8);
    merge_across(k, 16);

    if (sl == 0) {
        int orign = g_perm[b][n];
        int outb = ((b * NN) + orign) * KNN;
#pragma unroll
        for (int j = 0; j < KNN; j++) g_knn[outb + j] = (int)(u32)(k[j] & 0xFFFFFFFFull);
    }
}

// ---------------- launch 4: fold BN into conv weights ----------------
__global__ void fold_kernel(const float* __restrict__ w0, const float* __restrict__ b0,
                            const float* __restrict__ g0, const float* __restrict__ be0,
                            const float* __restrict__ m0, const float* __restrict__ v0,
                            const float* __restrict__ w1, const float* __restrict__ b1,
                            const float* __restrict__ g1, const float* __restrict__ be1,
                            const float* __restrict__ m1, const float* __restrict__ v1) {
    int tid = threadIdx.x;
    if (tid < FEAT) {
        float inv0 = g0[tid] / sqrtf(v0[tid] + EPS);
        g_w0f[tid * 3 + 0] = w0[tid * 3 + 0] * inv0;
        g_w0f[tid * 3 + 1] = w0[tid * 3 + 1] * inv0;
        g_w0f[tid * 3 + 2] = w0[tid * 3 + 2] * inv0;
        g_b0f[tid] = (b0[tid] - m0[tid]) * inv0 + be0[tid];
        float inv1 = g1[tid] / sqrtf(v1[tid] + EPS);
        g_b1f[tid] = (b1[tid] - m1[tid]) * inv1 + be1[tid];
    }
    for (int i = tid; i < FEAT * FEAT; i += blockDim.x) {
        int cout = i / FEAT, cin = i % FEAT;
        float inv1 = g1[cout] / sqrtf(v1[cout] + EPS);
        g_w1t[cin * FEAT + cout] = w1[cout * FEAT + cin] * inv1;
    }
}

// ---------------- launch 5: transpose local_feat (B,64,M) -> (B,M,64) ----------------
__global__ void __launch_bounds__(256) transpose_kernel(const float* __restrict__ lf) {
    __shared__ float tile[64][65];
    int b = blockIdx.y;
    int m0 = blockIdx.x * 64;
    int tid = threadIdx.x;
#pragma unroll
    for (int r = 0; r < 16; r++) {
        int c  = (tid >> 6) + (r << 2);
        int mm = tid & 63;
        tile[c][mm] = lf[((size_t)(b * FEAT + c)) * MM + m0 + mm];
    }
    __syncthreads();
#pragma unroll
    for (int r = 0; r < 16; r++) {
        int mm = (tid >> 6) + (r << 2);
        int c  = tid & 63;
        g_lft[((size_t)(b * MM + m0 + mm)) * FEAT + c] = tile[c][mm];
    }
}

// ---------------- launch 6: fused MLP + gather + blend ----------------
__global__ void __launch_bounds__(256) mlp_kernel(const float* __restrict__ orig,
                                                  const float* __restrict__ query,
                                                  const float* __restrict__ w2,
                                                  const float* __restrict__ b2,
                                                  float* __restrict__ out) {
    __shared__ float  w1s[FEAT * FEAT];
    __shared__ float  f0s[4][FEAT * K4];
    __shared__ float4 rel4[4][KNN];
    __shared__ int    idxs[4][KNN];
    __shared__ float  red[4][2][8];
    __shared__ float  outs[4][FEAT];

    int tid = threadIdx.x;
    int g = tid >> 6;
    int c = tid & 63;
    int b = blockIdx.y;

    for (int i = tid; i < FEAT * FEAT; i += 256) w1s[i] = g_w1t[i];

    float w00 = g_w0f[c * 3 + 0], w01 = g_w0f[c * 3 + 1], w02 = g_w0f[c * 3 + 2];
    float bb0 = g_b0f[c];
    float bb1 = g_b1f[c];
    float w2a = w2[c], w2b = w2[FEAT + c];
    float b2v = b2[0];

    for (int it = 0; it < QPB / 4; ++it) {
        int n = blockIdx.x * QPB + it * 4 + g;

        if (c < KNN) idxs[g][c] = g_knn[(((size_t)b * NN) + n) * KNN + c];
        __syncthreads();

        float p0 = g_lft[(((size_t)b * MM) + idxs[g][0]) * FEAT + c];
        float p1 = g_lft[(((size_t)b * MM) + idxs[g][1]) * FEAT + c];
        float p2 = g_lft[(((size_t)b * MM) + idxs[g][2]) * FEAT + c];
        float p3 = g_lft[(((size_t)b * MM) + idxs[g][3]) * FEAT + c];

        if (c < 48) {
            int j = c / 3;
            int a = c - j * 3;
            int m = idxs[g][j];
            float qa = query[((size_t)(b * 3 + a)) * NN + n];
            ((float*)&rel4[g][j])[a] = orig[((size_t)(b * 3 + a)) * MM + m] - qa;
        }
        __syncthreads();

        float fg = 0.f;
        float f0k0 = 0.f, f0k1 = 0.f, f0k2 = 0.f, f0k3 = 0.f;
#pragma unroll
        for (int j = 0; j < KNN; j++) {
            float4 r = rel4[g][j];
            float f = fmaf(w00, r.x, fmaf(w01, r.y, fmaf(w02, r.z, bb0)));
            f = fmaxf(f, 0.f);
            fg = fmaxf(fg, f);
            if (j == 0) f0k0 = f;
            if (j == 1) f0k1 = f;
            if (j == 2) f0k2 = f;
            if (j == 3) f0k3 = f;
        }
        *(float4*)&f0s[g][c * 4] = make_float4(f0k0, f0k1, f0k2, f0k3);
        __syncthreads();

        float a0 = bb1, a1 = bb1, a2 = bb1, a3 = bb1;
#pragma unroll 8
        for (int cin = 0; cin < FEAT; ++cin) {
            float wv = w1s[cin * FEAT + c];
            float4 f = *(float4*)&f0s[g][cin * 4];
            a0 = fmaf(wv, f.x, a0);
            a1 = fmaf(wv, f.y, a1);
            a2 = fmaf(wv, f.z, a2);
            a3 = fmaf(wv, f.w, a3);
        }
        float r0 = fmaxf(a0, 0.f), r1 = fmaxf(a1, 0.f), r2 = fmaxf(a2, 0.f), r3 = fmaxf(a3, 0.f);

        float t0 = w2a * r0, t1 = w2a * r1, t2 = w2a * r2, t3 = w2a * r3;
        float u = w2b * fg;
#pragma unroll
        for (int off = 16; off; off >>= 1) {
            t0 += __shfl_down_sync(0xffffffffu, t0, off);
            t1 += __shfl_down_sync(0xffffffffu, t1, off);
            t2 += __shfl_down_sync(0xffffffffu, t2, off);
            t3 += __shfl_down_sync(0xffffffffu, t3, off);
            u  += __shfl_down_sync(0xffffffffu, u, off);
        }
        if ((c & 31) == 0) {
            float* rr = red[g][c >> 5];
            rr[0] = t0; rr[1] = t1; rr[2] = t2; rr[3] = t3; rr[4] = u;
        }
        __syncthreads();

        float base = red[g][0][4] + red[g][1][4] + b2v;
        float z0 = red[g][0][0] + red[g][1][0] + base;
        float z1 = red[g][0][1] + red[g][1][1] + base;
        float z2 = red[g][0][2] + red[g][1][2] + base;
        float z3 = red[g][0][3] + red[g][1][3] + base;
        float wg0 = 1.f / (1.f + expf(-z0));
        float wg1 = 1.f / (1.f + expf(-z1));
        float wg2 = 1.f / (1.f + expf(-z2));
        float wg3 = 1.f / (1.f + expf(-z3));

        float o = (1.f - wg0) * r0 + wg0 * p0;
        o      += (1.f - wg1) * r1 + wg1 * p1;
        o      += (1.f - wg2) * r2 + wg2 * p2;
        o      += (1.f - wg3) * r3 + wg3 * p3;

        outs[g][c] = o;
        __syncthreads();

        int c2 = tid >> 2, g2 = tid & 3;
        out[((size_t)(b * FEAT + c2)) * NN + blockIdx.x * QPB + it * 4 + g2] = outs[g2][c2];
        __syncthreads();
    }
}

// ---------------- launch ----------------
extern "C" void kernel_launch(void* const* d_in, const int* in_sizes, int n_in,
                              void* d_out, int out_size) {
    const float* orig  = (const float*)d_in[0];
    const float* query = (const float*)d_in[1];
    const float* lf    = (const float*)d_in[2];
    const float* w0  = (const float*)d_in[3];
    const float* b0  = (const float*)d_in[4];
    const float* g0  = (const float*)d_in[5];
    const float* be0 = (const float*)d_in[6];
    const float* m0  = (const float*)d_in[7];
    const float* v0  = (const float*)d_in[8];
    const float* w1  = (const float*)d_in[9];
    const float* b1  = (const float*)d_in[10];
    const float* g1  = (const float*)d_in[11];
    const float* be1 = (const float*)d_in[12];
    const float* m1  = (const float*)d_in[13];
    const float* v1  = (const float*)d_in[14];
    const float* w2  = (const float*)d_in[15];
    const float* b2  = (const float*)d_in[16];
    float* out = (float*)d_out;

    keys_kernel<<<dim3(NN / 256, BB), 256>>>(query, orig);          // launch 0
    scan_kernel<<<dim3(BB, 2), 1024>>>();                           // launch 1
    scatters_kernel<<<dim3(NN / 256, BB), 256>>>(query, orig);      // launch 2
    knn_kernel<<<dim3(NN / 32, BB), 128>>>();                       // launch 3  <-- ncu slot
    fold_kernel<<<1, 256>>>(w0, b0, g0, be0, m0, v0, w1, b1, g1, be1, m1, v1);
    transpose_kernel<<<dim3(MM / 64, BB), 256>>>(lf);
    mlp_kernel<<<dim3(NN / QPB, BB), 256>>>(orig, query, w2, b2, out);
}